// round 1
// baseline (speedup 1.0000x reference)
#include <cuda_runtime.h>
#include <math.h>

// ---------------- static scratch (no allocations allowed) ----------------
__device__ float g_conv1[128*64*55*55];
__device__ float g_pool1[128*64*27*27];
__device__ float g_conv2[128*192*27*27];
__device__ float g_pool2[128*192*13*13];
__device__ float g_conv3[128*384*13*13];
__device__ float g_conv4[128*256*13*13];
__device__ float g_conv5[128*256*13*13];
__device__ float g_pool5[128*256*6*6];
__device__ float g_fc1[128*4096];
__device__ float g_fc2[128*4096];
__device__ float g_h[128*128];
__device__ float g_soft[128*128];

// ---------------- implicit-GEMM convolution ----------------
// C[oc][p] = sum_k W[oc][k] * im2col[k][p],  p = (n, oh, ow), k = (ic, kh, kw)
// Tiles: 64 oc x 64 p, BK=16, 256 threads, 4x4 micro-tile per thread.
template<int CIN,int KW,int S,int PD,int HIN,int HOUT,int OC,bool RELU>
__global__ __launch_bounds__(256) void conv_gemm(
    const float* __restrict__ in, const float* __restrict__ w,
    const float* __restrict__ bias, float* __restrict__ out)
{
    constexpr int KK = KW*KW;
    constexpr int KD = CIN*KK;
    constexpr int HW = HOUT*HOUT;

    __shared__ float sA[16][64];   // [kk][oc]
    __shared__ float sB[16][64];   // [kk][p]

    const int tid = threadIdx.x;
    const int tx = tid & 15;       // p group
    const int ty = tid >> 4;       // oc group
    const int ocBase = blockIdx.y * 64;
    const int pBase  = blockIdx.x * 64;

    // ---- B (im2col) decode: fixed p per thread across all k-steps ----
    const int pp   = tid & 63;
    const int kkB0 = tid >> 6;                 // 0..3
    const int p  = pBase + pp;
    const int n  = p / HW;
    const int q  = p - n*HW;
    const int oh = q / HOUT;
    const int ow = q - oh*HOUT;
    const int ihb = oh*S - PD;
    const int iwb = ow*S - PD;
    const float* inN = in + n*CIN*HIN*HIN;

    // ---- A mapping: thread loads 4 consecutive k of one oc row ----
    const int ocA  = tid >> 2;                 // 0..63
    const int kkA0 = (tid & 3) * 4;            // 0,4,8,12
    const float* wrow = w + (ocBase + ocA)*KD;

    float acc[4][4];
    #pragma unroll
    for (int i=0;i<4;i++)
        #pragma unroll
        for (int j=0;j<4;j++) acc[i][j]=0.f;

    for (int k0 = 0; k0 < KD; k0 += 16) {
        // load A tile
        #pragma unroll
        for (int i=0;i<4;i++) {
            int kk = kkA0 + i;
            int kg = k0 + kk;
            sA[kk][ocA] = (kg < KD) ? wrow[kg] : 0.f;
        }
        // load B tile (im2col gather)
        #pragma unroll
        for (int i=0;i<4;i++) {
            int kk = kkB0 + i*4;
            int kg = k0 + kk;
            float v = 0.f;
            if (kg < KD) {
                int ic  = kg / KK;
                int r   = kg - ic*KK;
                int kh  = r / KW;
                int kwv = r - kh*KW;
                int ih = ihb + kh, iw = iwb + kwv;
                if (ih >= 0 && ih < HIN && iw >= 0 && iw < HIN)
                    v = __ldg(&inN[(ic*HIN + ih)*HIN + iw]);
            }
            sB[kk][pp] = v;
        }
        __syncthreads();
        #pragma unroll
        for (int kk=0; kk<16; kk++) {
            float4 a = *(const float4*)&sA[kk][ty*4];
            float4 b = *(const float4*)&sB[kk][tx*4];
            acc[0][0] += a.x*b.x; acc[0][1] += a.x*b.y; acc[0][2] += a.x*b.z; acc[0][3] += a.x*b.w;
            acc[1][0] += a.y*b.x; acc[1][1] += a.y*b.y; acc[1][2] += a.y*b.z; acc[1][3] += a.y*b.w;
            acc[2][0] += a.z*b.x; acc[2][1] += a.z*b.y; acc[2][2] += a.z*b.z; acc[2][3] += a.z*b.w;
            acc[3][0] += a.w*b.x; acc[3][1] += a.w*b.y; acc[3][2] += a.w*b.z; acc[3][3] += a.w*b.w;
        }
        __syncthreads();
    }

    #pragma unroll
    for (int i=0;i<4;i++) {
        int oc = ocBase + ty*4 + i;
        float bv = bias[oc];
        #pragma unroll
        for (int j=0;j<4;j++) {
            int pe = pBase + tx*4 + j;
            int ne = pe / HW;
            int qe = pe - ne*HW;
            float v = acc[i][j] + bv;
            if (RELU) v = fmaxf(v, 0.f);
            out[(ne*OC + oc)*HW + qe] = v;
        }
    }
}

// ---------------- dense GEMM for FC layers ----------------
// out[p][oc] = sum_k x[p][k] * w[oc][k] + bias[oc]   (K % 16 == 0, % 4 == 0)
template<bool RELU>
__global__ __launch_bounds__(256) void fc_gemm(
    const float* __restrict__ x, const float* __restrict__ w,
    const float* __restrict__ bias, float* __restrict__ out,
    int N, int K)
{
    __shared__ float sA[16][64];   // [kk][oc]
    __shared__ float sB[16][64];   // [kk][p]

    const int tid = threadIdx.x;
    const int tx = tid & 15;
    const int ty = tid >> 4;
    const int ocBase = blockIdx.y * 64;
    const int pBase  = blockIdx.x * 64;

    const int rA = tid >> 2;        // 0..63 (oc-local / p-local)
    const int c0 = (tid & 3) * 4;   // 0,4,8,12
    const float* wrow = w + (size_t)(ocBase + rA)*K;
    const float* xrow = x + (size_t)(pBase  + rA)*K;

    float acc[4][4];
    #pragma unroll
    for (int i=0;i<4;i++)
        #pragma unroll
        for (int j=0;j<4;j++) acc[i][j]=0.f;

    for (int k0 = 0; k0 < K; k0 += 16) {
        float4 wa = *(const float4*)&wrow[k0 + c0];
        float4 xa = *(const float4*)&xrow[k0 + c0];
        sA[c0+0][rA]=wa.x; sA[c0+1][rA]=wa.y; sA[c0+2][rA]=wa.z; sA[c0+3][rA]=wa.w;
        sB[c0+0][rA]=xa.x; sB[c0+1][rA]=xa.y; sB[c0+2][rA]=xa.z; sB[c0+3][rA]=xa.w;
        __syncthreads();
        #pragma unroll
        for (int kk=0; kk<16; kk++) {
            float4 a = *(const float4*)&sA[kk][ty*4];
            float4 b = *(const float4*)&sB[kk][tx*4];
            acc[0][0] += a.x*b.x; acc[0][1] += a.x*b.y; acc[0][2] += a.x*b.z; acc[0][3] += a.x*b.w;
            acc[1][0] += a.y*b.x; acc[1][1] += a.y*b.y; acc[1][2] += a.y*b.z; acc[1][3] += a.y*b.w;
            acc[2][0] += a.z*b.x; acc[2][1] += a.z*b.y; acc[2][2] += a.z*b.z; acc[2][3] += a.z*b.w;
            acc[3][0] += a.w*b.x; acc[3][1] += a.w*b.y; acc[3][2] += a.w*b.z; acc[3][3] += a.w*b.w;
        }
        __syncthreads();
    }

    #pragma unroll
    for (int i=0;i<4;i++) {
        int oc = ocBase + ty*4 + i;
        float bv = bias[oc];
        #pragma unroll
        for (int j=0;j<4;j++) {
            int pe = pBase + tx*4 + j;
            float v = acc[i][j] + bv;
            if (RELU) v = fmaxf(v, 0.f);
            out[(size_t)pe*N + oc] = v;
        }
    }
}

// ---------------- 3x3 stride-2 VALID maxpool ----------------
template<int HIN,int HOUT>
__global__ void maxpool3s2(const float* __restrict__ in, float* __restrict__ out, int total)
{
    int idx = blockIdx.x*256 + threadIdx.x;
    if (idx >= total) return;
    int ow = idx % HOUT;
    int t  = idx / HOUT;
    int oh = t % HOUT;
    int nc = t / HOUT;
    const float* p = in + nc*HIN*HIN + (oh*2)*HIN + ow*2;
    float m = p[0];
    #pragma unroll
    for (int a=0;a<3;a++)
        #pragma unroll
        for (int b=0;b<3;b++)
            m = fmaxf(m, p[a*HIN+b]);
    out[idx] = m;
}

// ---------------- PQ head: cosine sims, softmax, soft/hard codes ----------------
// One block per (b, l). 256 threads = one per codeword.
__global__ void pq_head(const float* __restrict__ h, const float* __restrict__ cb,
                        float* __restrict__ gsoft, float* __restrict__ oh_,
                        float* __restrict__ ohard, float* __restrict__ osoft)
{
    __shared__ float xs[32];
    __shared__ float pe[256];
    __shared__ float sv[256];
    __shared__ int   si[256];

    const int tid = threadIdx.x;
    const int b = blockIdx.x >> 2;
    const int l = blockIdx.x & 3;

    if (tid < 32) xs[tid] = h[b*128 + l*32 + tid];
    __syncthreads();

    float xn2 = 0.f;
    #pragma unroll
    for (int d=0; d<32; d++) xn2 += xs[d]*xs[d];

    const float* cbl = cb + (l*256)*32;
    const float* ck  = cbl + tid*32;
    float dot=0.f, cn2=0.f;
    #pragma unroll
    for (int d=0; d<32; d++) { float c = ck[d]; dot += xs[d]*c; cn2 += c*c; }
    float s = dot / fmaxf(sqrtf(xn2)*sqrtf(cn2), 1e-8f);

    // argmax (first index wins ties, matching jnp.argmax)
    sv[tid]=s; si[tid]=tid;
    __syncthreads();
    for (int off=128; off>0; off>>=1) {
        if (tid<off) {
            float ov=sv[tid+off]; int oi=si[tid+off];
            if (ov>sv[tid] || (ov==sv[tid] && oi<si[tid])) { sv[tid]=ov; si[tid]=oi; }
        }
        __syncthreads();
    }
    float mx = sv[0]; int idx = si[0];
    __syncthreads();

    // softmax(GAMA * sim)
    float e = expf(20.f*(s - mx));
    pe[tid]=e; sv[tid]=e;
    __syncthreads();
    for (int off=128; off>0; off>>=1) {
        if (tid<off) sv[tid] += sv[tid+off];
        __syncthreads();
    }
    float denom = sv[0];

    if (tid < 32) {
        // soft = sum_k p_k * cb[l][k][:], then L2-normalize
        float acc = 0.f;
        for (int k=0;k<256;k++) acc += pe[k]*cbl[k*32+tid];
        acc /= denom;
        float n2 = acc*acc;
        #pragma unroll
        for (int m=16;m;m>>=1) n2 += __shfl_xor_sync(0xffffffffu, n2, m);
        float svv = acc / fmaxf(sqrtf(n2), 1e-12f);
        int o = b*128 + l*32 + tid;
        osoft[o] = svv;
        gsoft[o] = svv;
        // hard = cb[l][idx][:] normalized
        float c = cbl[idx*32+tid];
        float h2 = c*c;
        #pragma unroll
        for (int m=16;m;m>>=1) h2 += __shfl_xor_sync(0xffffffffu, h2, m);
        ohard[o] = c / fmaxf(sqrtf(h2), 1e-12f);
        // pass through h
        oh_[o] = xs[tid];
    }
}

// ---------------- recon: leaky_relu(soft @ rw^T, 0.01) ----------------
__global__ void recon_kernel(const float* __restrict__ soft, const float* __restrict__ rw,
                             float* __restrict__ out)
{
    __shared__ float s[128];
    const int b = blockIdx.x, tid = threadIdx.x;
    if (tid < 128) s[tid] = soft[b*128 + tid];
    __syncthreads();
    for (int r = tid; r < 300; r += 256) {
        const float* wr = rw + r*128;
        float a = 0.f;
        #pragma unroll 8
        for (int k=0;k<128;k++) a += s[k]*wr[k];
        out[b*300 + r] = a > 0.f ? a : 0.01f*a;
    }
}

// ---------------- launch ----------------
extern "C" void kernel_launch(void* const* d_in, const int* in_sizes, int n_in,
                              void* d_out, int out_size)
{
    const float* x   = (const float*)d_in[0];
    const float* w1  = (const float*)d_in[1];
    const float* b1  = (const float*)d_in[2];
    const float* w2  = (const float*)d_in[3];
    const float* b2  = (const float*)d_in[4];
    const float* w3  = (const float*)d_in[5];
    const float* b3  = (const float*)d_in[6];
    const float* w4  = (const float*)d_in[7];
    const float* b4  = (const float*)d_in[8];
    const float* w5  = (const float*)d_in[9];
    const float* b5  = (const float*)d_in[10];
    const float* cw1 = (const float*)d_in[11];
    const float* cb1 = (const float*)d_in[12];
    const float* cw2 = (const float*)d_in[13];
    const float* cb2 = (const float*)d_in[14];
    const float* fw  = (const float*)d_in[15];
    const float* fb  = (const float*)d_in[16];
    const float* cbk = (const float*)d_in[17];
    const float* rw  = (const float*)d_in[18];

    float* out = (float*)d_out;
    float* out_h    = out;            // 128*128
    float* out_hard = out + 16384;    // 128*128
    float* out_soft = out + 32768;    // 128*128
    float* out_rec  = out + 49152;    // 128*300

    float *c1,*p1v,*c2,*p2v,*c3,*c4,*c5,*p5,*f1,*f2,*hh,*sf;
    cudaGetSymbolAddress((void**)&c1,  g_conv1);
    cudaGetSymbolAddress((void**)&p1v, g_pool1);
    cudaGetSymbolAddress((void**)&c2,  g_conv2);
    cudaGetSymbolAddress((void**)&p2v, g_pool2);
    cudaGetSymbolAddress((void**)&c3,  g_conv3);
    cudaGetSymbolAddress((void**)&c4,  g_conv4);
    cudaGetSymbolAddress((void**)&c5,  g_conv5);
    cudaGetSymbolAddress((void**)&p5,  g_pool5);
    cudaGetSymbolAddress((void**)&f1,  g_fc1);
    cudaGetSymbolAddress((void**)&f2,  g_fc2);
    cudaGetSymbolAddress((void**)&hh,  g_h);
    cudaGetSymbolAddress((void**)&sf,  g_soft);

    // conv1: 3->64, k11 s4 p2, 224 -> 55   (P = 128*3025 = 387200)
    conv_gemm<3,11,4,2,224,55,64,true><<<dim3(6050,1),256>>>(x, w1, b1, c1);
    maxpool3s2<55,27><<<(128*64*27*27 + 255)/256, 256>>>(c1, p1v, 128*64*27*27);
    // conv2: 64->192, k5 s1 p2, 27 -> 27   (P = 128*729 = 93312)
    conv_gemm<64,5,1,2,27,27,192,true><<<dim3(1458,3),256>>>(p1v, w2, b2, c2);
    maxpool3s2<27,13><<<(128*192*13*13 + 255)/256, 256>>>(c2, p2v, 128*192*13*13);
    // conv3-5: k3 s1 p1, 13 -> 13          (P = 128*169 = 21632)
    conv_gemm<192,3,1,1,13,13,384,true><<<dim3(338,6),256>>>(p2v, w3, b3, c3);
    conv_gemm<384,3,1,1,13,13,256,true><<<dim3(338,4),256>>>(c3, w4, b4, c4);
    conv_gemm<256,3,1,1,13,13,256,true><<<dim3(338,4),256>>>(c4, w5, b5, c5);
    maxpool3s2<13,6><<<(128*256*6*6 + 255)/256, 256>>>(c5, p5, 128*256*6*6);
    // FC stack
    fc_gemm<true ><<<dim3(2,64),256>>>(p5, cw1, cb1, f1, 4096, 9216);
    fc_gemm<true ><<<dim3(2,64),256>>>(f1, cw2, cb2, f2, 4096, 4096);
    fc_gemm<false><<<dim3(2, 2),256>>>(f2, fw,  fb,  hh,  128, 4096);
    // PQ head + recon
    pq_head<<<512,256>>>(hh, cbk, sf, out_h, out_hard, out_soft);
    recon_kernel<<<128,256>>>(sf, rw, out_rec);
}

// round 3
// speedup vs baseline: 1.2630x; 1.2630x over previous
#include <cuda_runtime.h>
#include <cuda_bf16.h>
#include <stdint.h>
#include <math.h>

// ---------------- static scratch (no allocations allowed) ----------------
__device__ float g_conv1[128*64*55*55];
__device__ float g_pool1[128*64*27*27];
__device__ float g_conv2[128*192*27*27];
__device__ float g_pool2[128*192*13*13];
__device__ float g_conv3[128*384*13*13];
__device__ float g_conv4[128*256*13*13];
__device__ float g_conv5[128*256*13*13];
__device__ float g_pool5[128*256*6*6];
__device__ float g_fc1[128*4096];
__device__ float g_fc2[128*4096];
__device__ float g_h[128*128];
__device__ float g_soft[128*128];

// ---------------- warp-MMA helpers (baseline PTX ISA, works on plain sm_100) --
__device__ __forceinline__ uint32_t smem_u32(const void* p) {
    uint32_t a;
    asm("{ .reg .u64 t; cvta.to.shared.u64 t, %1; cvt.u32.u64 %0, t; }" : "=r"(a) : "l"(p));
    return a;
}
__device__ __forceinline__ void ldsm4(uint32_t addr, uint32_t& r0, uint32_t& r1,
                                      uint32_t& r2, uint32_t& r3) {
    asm volatile("ldmatrix.sync.aligned.m8n8.x4.shared.b16 {%0,%1,%2,%3}, [%4];"
        : "=r"(r0), "=r"(r1), "=r"(r2), "=r"(r3) : "r"(addr));
}
__device__ __forceinline__ void mma16816(float* c, const uint32_t* a, const uint32_t* b) {
    asm volatile("mma.sync.aligned.m16n8k16.row.col.f32.bf16.bf16.f32 "
        "{%0,%1,%2,%3}, {%4,%5,%6,%7}, {%8,%9}, {%0,%1,%2,%3};"
        : "+f"(c[0]), "+f"(c[1]), "+f"(c[2]), "+f"(c[3])
        : "r"(a[0]), "r"(a[1]), "r"(a[2]), "r"(a[3]), "r"(b[0]), "r"(b[1]));
}

// ---------------- tensor-core GEMM (implicit-GEMM conv or dense FC) ----------
// D[p][oc] = sum_k A[p,k] * W[oc,k], fp32 accum, 3-term bf16 split:
//   A*B ~= Ah*Bh + Al*Bh + Ah*Bl   (residual ~2^-17)
// Tile: BM=128 pixels x BN=64 ocs x BK=32. 8 warps (4 m x 2 n), warp = 32x32.
template<int KDIM, int OCTOT, bool RELU, bool IM2COL,
         int CIN, int KW, int S, int PD, int HIN, int HOUT>
__global__ __launch_bounds__(256, 2) void wmma_gemm(
    const float* __restrict__ A_in, const float* __restrict__ Wmat,
    const float* __restrict__ bias, float* __restrict__ out)
{
    constexpr int BK  = 32;
    constexpr int LDA = BK + 8;                 // padded bf16 row stride (40)
    constexpr int CH  = (KDIM + BK - 1) / BK;
    constexpr int KKc = KW * KW;
    constexpr int HW  = HOUT * HOUT;

    __shared__ __align__(16) __nv_bfloat16 Ah[128 * LDA];
    __shared__ __align__(16) __nv_bfloat16 Al[128 * LDA];
    __shared__ __align__(16) __nv_bfloat16 Bh[64  * LDA];
    __shared__ __align__(16) __nv_bfloat16 Bl[64  * LDA];

    const int tid  = threadIdx.x;
    const int wid  = tid >> 5;
    const int lane = tid & 31;
    const int wm   = wid & 3;                   // m-warp 0..3 (rows wm*32)
    const int wn   = wid >> 2;                  // n-warp 0..1 (cols wn*32)
    const int ocBase = blockIdx.y * 64;

    // ---- A fill decode: thread -> (row, 16-col half) ----
    const int row = tid >> 1;
    const int c0  = (tid & 1) * 16;
    const int p   = blockIdx.x * 128 + row;
    int ihb = 0, iwb = 0;
    const float* inN = A_in;
    if (IM2COL) {
        int n = p / HW; int q = p - n * HW;
        int oh = q / HOUT, ow = q - oh * HOUT;
        ihb = oh * S - PD; iwb = ow * S - PD;
        inN = A_in + (size_t)n * CIN * HIN * HIN;
    }

    float acc[2][4][4];
    #pragma unroll
    for (int i=0;i<2;i++)
        #pragma unroll
        for (int j=0;j<4;j++)
            #pragma unroll
            for (int k=0;k<4;k++) acc[i][j][k]=0.f;

    const uint32_t aH = smem_u32(Ah), aL = smem_u32(Al);
    const uint32_t bH = smem_u32(Bh), bL = smem_u32(Bl);
    const int g  = lane >> 3;                   // ldmatrix group
    const int rr = lane & 7;

    for (int ci = 0; ci < CH; ci++) {
        const int kb = ci * BK;

        // ---- fill A (128 x 32) hi/lo ----
        #pragma unroll
        for (int cc = 0; cc < 16; cc += 2) {
            float v0 = 0.f, v1 = 0.f;
            #pragma unroll
            for (int e = 0; e < 2; e++) {
                int k = kb + c0 + cc + e;
                float v = 0.f;
                if (k < KDIM) {
                    if (!IM2COL) {
                        v = A_in[(size_t)p * KDIM + k];
                    } else {
                        int ic = k / KKc; int r2 = k - ic * KKc;
                        int kh = r2 / KW; int kw2 = r2 - kh * KW;
                        int ih = ihb + kh, iw = iwb + kw2;
                        if (ih >= 0 && ih < HIN && iw >= 0 && iw < HIN)
                            v = __ldg(&inN[(ic * HIN + ih) * HIN + iw]);
                    }
                }
                if (e == 0) v0 = v; else v1 = v;
            }
            __nv_bfloat162 hp, lp;
            hp.x = __float2bfloat16(v0); hp.y = __float2bfloat16(v1);
            lp.x = __float2bfloat16(v0 - __bfloat162float(hp.x));
            lp.y = __float2bfloat16(v1 - __bfloat162float(hp.y));
            int off = row * LDA + c0 + cc;
            *(__nv_bfloat162*)&Ah[off] = hp;
            *(__nv_bfloat162*)&Al[off] = lp;
        }

        // ---- fill B (64 x 32) hi/lo (threads 0..127) ----
        if (tid < 128) {
            int br = tid >> 1;
            const float* wr = Wmat + (size_t)(ocBase + br) * KDIM;
            #pragma unroll
            for (int cc = 0; cc < 16; cc += 2) {
                int k = kb + c0 + cc;
                float v0 = (k     < KDIM) ? wr[k]     : 0.f;
                float v1 = (k + 1 < KDIM) ? wr[k + 1] : 0.f;
                __nv_bfloat162 hp, lp;
                hp.x = __float2bfloat16(v0); hp.y = __float2bfloat16(v1);
                lp.x = __float2bfloat16(v0 - __bfloat162float(hp.x));
                lp.y = __float2bfloat16(v1 - __bfloat162float(hp.y));
                int off = br * LDA + c0 + cc;
                *(__nv_bfloat162*)&Bh[off] = hp;
                *(__nv_bfloat162*)&Bl[off] = lp;
            }
        }
        __syncthreads();

        // ---- compute: 2 k-steps of 16 ----
        #pragma unroll
        for (int ks = 0; ks < 2; ks++) {
            const int kc = ks * 16;
            uint32_t fah[2][4], fal[2][4], fbh[4][2], fbl[4][2];
            // A fragments: mt in {0,1}, 16x16 tile each
            #pragma unroll
            for (int mt = 0; mt < 2; mt++) {
                uint32_t off = (uint32_t)((wm*32 + mt*16 + (g&1)*8 + rr) * LDA
                                          + kc + (g>>1)*8) * 2u;
                ldsm4(aH + off, fah[mt][0], fah[mt][1], fah[mt][2], fah[mt][3]);
                ldsm4(aL + off, fal[mt][0], fal[mt][1], fal[mt][2], fal[mt][3]);
            }
            // B fragments: n-tile pairs np in {0,1} -> 4 n-tiles of 8
            #pragma unroll
            for (int np = 0; np < 2; np++) {
                uint32_t off = (uint32_t)((wn*32 + np*16 + (g>>1)*8 + rr) * LDA
                                          + kc + (g&1)*8) * 2u;
                uint32_t r0,r1,r2,r3;
                ldsm4(bH + off, r0,r1,r2,r3);
                fbh[2*np][0]=r0; fbh[2*np][1]=r1; fbh[2*np+1][0]=r2; fbh[2*np+1][1]=r3;
                ldsm4(bL + off, r0,r1,r2,r3);
                fbl[2*np][0]=r0; fbl[2*np][1]=r1; fbl[2*np+1][0]=r2; fbl[2*np+1][1]=r3;
            }
            #pragma unroll
            for (int mt = 0; mt < 2; mt++)
                #pragma unroll
                for (int nt = 0; nt < 4; nt++) {
                    mma16816(acc[mt][nt], fah[mt], fbh[nt]);
                    mma16816(acc[mt][nt], fal[mt], fbh[nt]);
                    mma16816(acc[mt][nt], fah[mt], fbl[nt]);
                }
        }
        __syncthreads();
    }

    // ---- epilogue: c-frag lane layout -> bias + relu -> NCHW / row-major ----
    #pragma unroll
    for (int mt = 0; mt < 2; mt++) {
        #pragma unroll
        for (int nt = 0; nt < 4; nt++) {
            int m0 = blockIdx.x * 128 + wm*32 + mt*16 + (lane >> 2);
            int n0 = ocBase + wn*32 + nt*8 + (lane & 3)*2;
            #pragma unroll
            for (int h = 0; h < 2; h++) {        // row, row+8
                int pe = m0 + h*8;
                #pragma unroll
                for (int cidx = 0; cidx < 2; cidx++) {
                    int oc = n0 + cidx;
                    float v = acc[mt][nt][h*2 + cidx] + __ldg(&bias[oc]);
                    if (RELU) v = fmaxf(v, 0.f);
                    if (IM2COL) {
                        int ne = pe / HW; int qe = pe - ne * HW;
                        out[((size_t)ne * OCTOT + oc) * HW + qe] = v;
                    } else {
                        out[(size_t)pe * OCTOT + oc] = v;
                    }
                }
            }
        }
    }
}

// ---------------- 3x3 stride-2 VALID maxpool ----------------
template<int HIN,int HOUT>
__global__ void maxpool3s2(const float* __restrict__ in, float* __restrict__ out, int total)
{
    int idx = blockIdx.x*256 + threadIdx.x;
    if (idx >= total) return;
    int ow = idx % HOUT;
    int t  = idx / HOUT;
    int oh = t % HOUT;
    int nc = t / HOUT;
    const float* p = in + nc*HIN*HIN + (oh*2)*HIN + ow*2;
    float m = p[0];
    #pragma unroll
    for (int a=0;a<3;a++)
        #pragma unroll
        for (int b=0;b<3;b++)
            m = fmaxf(m, p[a*HIN+b]);
    out[idx] = m;
}

// ---------------- PQ head ----------------
__global__ void pq_head(const float* __restrict__ h, const float* __restrict__ cb,
                        float* __restrict__ gsoft, float* __restrict__ oh_,
                        float* __restrict__ ohard, float* __restrict__ osoft)
{
    __shared__ float xs[32];
    __shared__ float pe[256];
    __shared__ float sv[256];
    __shared__ int   si[256];

    const int tid = threadIdx.x;
    const int b = blockIdx.x >> 2;
    const int l = blockIdx.x & 3;

    if (tid < 32) xs[tid] = h[b*128 + l*32 + tid];
    __syncthreads();

    float xn2 = 0.f;
    #pragma unroll
    for (int d=0; d<32; d++) xn2 += xs[d]*xs[d];

    const float* cbl = cb + (l*256)*32;
    const float* ck  = cbl + tid*32;
    float dot=0.f, cn2=0.f;
    #pragma unroll
    for (int d=0; d<32; d++) { float c = ck[d]; dot += xs[d]*c; cn2 += c*c; }
    float s = dot / fmaxf(sqrtf(xn2)*sqrtf(cn2), 1e-8f);

    sv[tid]=s; si[tid]=tid;
    __syncthreads();
    for (int off=128; off>0; off>>=1) {
        if (tid<off) {
            float ov=sv[tid+off]; int oi=si[tid+off];
            if (ov>sv[tid] || (ov==sv[tid] && oi<si[tid])) { sv[tid]=ov; si[tid]=oi; }
        }
        __syncthreads();
    }
    float mx = sv[0]; int idx = si[0];
    __syncthreads();

    float e = expf(20.f*(s - mx));
    pe[tid]=e; sv[tid]=e;
    __syncthreads();
    for (int off=128; off>0; off>>=1) {
        if (tid<off) sv[tid] += sv[tid+off];
        __syncthreads();
    }
    float denom = sv[0];

    if (tid < 32) {
        float acc = 0.f;
        for (int k=0;k<256;k++) acc += pe[k]*cbl[k*32+tid];
        acc /= denom;
        float n2 = acc*acc;
        #pragma unroll
        for (int m=16;m;m>>=1) n2 += __shfl_xor_sync(0xffffffffu, n2, m);
        float svv = acc / fmaxf(sqrtf(n2), 1e-12f);
        int o = b*128 + l*32 + tid;
        osoft[o] = svv;
        gsoft[o] = svv;
        float c = cbl[idx*32+tid];
        float h2 = c*c;
        #pragma unroll
        for (int m=16;m;m>>=1) h2 += __shfl_xor_sync(0xffffffffu, h2, m);
        ohard[o] = c / fmaxf(sqrtf(h2), 1e-12f);
        oh_[o] = xs[tid];
    }
}

// ---------------- recon: leaky_relu(soft @ rw^T, 0.01) ----------------
__global__ void recon_kernel(const float* __restrict__ soft, const float* __restrict__ rw,
                             float* __restrict__ out)
{
    __shared__ float s[128];
    const int b = blockIdx.x, tid = threadIdx.x;
    if (tid < 128) s[tid] = soft[b*128 + tid];
    __syncthreads();
    for (int r = tid; r < 300; r += 256) {
        const float* wr = rw + r*128;
        float a = 0.f;
        #pragma unroll 8
        for (int k=0;k<128;k++) a += s[k]*wr[k];
        out[b*300 + r] = a > 0.f ? a : 0.01f*a;
    }
}

// ---------------- launch ----------------
extern "C" void kernel_launch(void* const* d_in, const int* in_sizes, int n_in,
                              void* d_out, int out_size)
{
    const float* x   = (const float*)d_in[0];
    const float* w1  = (const float*)d_in[1];
    const float* b1  = (const float*)d_in[2];
    const float* w2  = (const float*)d_in[3];
    const float* b2  = (const float*)d_in[4];
    const float* w3  = (const float*)d_in[5];
    const float* b3  = (const float*)d_in[6];
    const float* w4  = (const float*)d_in[7];
    const float* b4  = (const float*)d_in[8];
    const float* w5  = (const float*)d_in[9];
    const float* b5  = (const float*)d_in[10];
    const float* cw1 = (const float*)d_in[11];
    const float* cb1 = (const float*)d_in[12];
    const float* cw2 = (const float*)d_in[13];
    const float* cb2 = (const float*)d_in[14];
    const float* fw  = (const float*)d_in[15];
    const float* fb  = (const float*)d_in[16];
    const float* cbk = (const float*)d_in[17];
    const float* rw  = (const float*)d_in[18];

    float* out = (float*)d_out;
    float* out_h    = out;
    float* out_hard = out + 16384;
    float* out_soft = out + 32768;
    float* out_rec  = out + 49152;

    float *c1,*p1v,*c2,*p2v,*c3,*c4,*c5,*p5,*f1,*f2,*hh,*sf;
    cudaGetSymbolAddress((void**)&c1,  g_conv1);
    cudaGetSymbolAddress((void**)&p1v, g_pool1);
    cudaGetSymbolAddress((void**)&c2,  g_conv2);
    cudaGetSymbolAddress((void**)&p2v, g_pool2);
    cudaGetSymbolAddress((void**)&c3,  g_conv3);
    cudaGetSymbolAddress((void**)&c4,  g_conv4);
    cudaGetSymbolAddress((void**)&c5,  g_conv5);
    cudaGetSymbolAddress((void**)&p5,  g_pool5);
    cudaGetSymbolAddress((void**)&f1,  g_fc1);
    cudaGetSymbolAddress((void**)&f2,  g_fc2);
    cudaGetSymbolAddress((void**)&hh,  g_h);
    cudaGetSymbolAddress((void**)&sf,  g_soft);

    // conv1: 3->64, k11 s4 p2, 224->55, P=387200 (3025 tiles)
    wmma_gemm<363, 64, true, true, 3,11,4,2,224,55><<<dim3(3025,1),256>>>(x, w1, b1, c1);
    maxpool3s2<55,27><<<(128*64*27*27 + 255)/256, 256>>>(c1, p1v, 128*64*27*27);
    // conv2: 64->192, k5 p2, 27->27, P=93312 (729 tiles x 3 oc-tiles)
    wmma_gemm<1600, 192, true, true, 64,5,1,2,27,27><<<dim3(729,3),256>>>(p1v, w2, b2, c2);
    maxpool3s2<27,13><<<(128*192*13*13 + 255)/256, 256>>>(c2, p2v, 128*192*13*13);
    // conv3: 192->384
    wmma_gemm<1728, 384, true, true, 192,3,1,1,13,13><<<dim3(169,6),256>>>(p2v, w3, b3, c3);
    // conv4: 384->256
    wmma_gemm<3456, 256, true, true, 384,3,1,1,13,13><<<dim3(169,4),256>>>(c3, w4, b4, c4);
    // conv5: 256->256
    wmma_gemm<2304, 256, true, true, 256,3,1,1,13,13><<<dim3(169,4),256>>>(c4, w5, b5, c5);
    maxpool3s2<13,6><<<(128*256*6*6 + 255)/256, 256>>>(c5, p5, 128*256*6*6);
    // FC stack (M = 128 batch rows)
    wmma_gemm<9216, 4096, true,  false, 1,1,1,0,1,1><<<dim3(1,64),256>>>(p5, cw1, cb1, f1);
    wmma_gemm<4096, 4096, true,  false, 1,1,1,0,1,1><<<dim3(1,64),256>>>(f1, cw2, cb2, f2);
    wmma_gemm<4096, 128,  false, false, 1,1,1,0,1,1><<<dim3(1,2), 256>>>(f2, fw,  fb,  hh);
    // PQ head + recon
    pq_head<<<512,256>>>(hh, cbk, sf, out_h, out_hard, out_soft);
    recon_kernel<<<128,256>>>(sf, rw, out_rec);
}

// round 5
// speedup vs baseline: 2.3003x; 1.8214x over previous
#include <cuda_runtime.h>
#include <cuda_bf16.h>
#include <stdint.h>
#include <math.h>

// ---------------- static scratch (no allocations allowed) ----------------
__device__ __nv_bfloat162 g_conv1[128*64*55*55];
__device__ __nv_bfloat162 g_pool1[128*64*27*27];
__device__ __nv_bfloat162 g_conv2[128*192*27*27];
__device__ __nv_bfloat162 g_pool2[128*192*13*13];
__device__ __nv_bfloat162 g_conv3[128*384*13*13];
__device__ __nv_bfloat162 g_conv4[128*256*13*13];
__device__ __nv_bfloat162 g_conv5[128*256*13*13];
__device__ __nv_bfloat162 g_pool5[128*256*6*6];
__device__ __nv_bfloat162 g_fc1[128*4096];
__device__ __nv_bfloat162 g_fc2[128*4096];
__device__ float g_h[128*128];
__device__ float g_soft[128*128];
__device__ float g_part[8*128*4096];

// prepped weights: bf16 hi/lo planes, K padded to mult of 32
__device__ __nv_bfloat16 wp1h[64*384],   wp1l[64*384];
__device__ __nv_bfloat16 wp2h[192*1600], wp2l[192*1600];
__device__ __nv_bfloat16 wp3h[384*1728], wp3l[384*1728];
__device__ __nv_bfloat16 wp4h[256*3456], wp4l[256*3456];
__device__ __nv_bfloat16 wp5h[256*2304], wp5l[256*2304];
__device__ __nv_bfloat16 wf1h[4096*9216],wf1l[4096*9216];
__device__ __nv_bfloat16 wf2h[4096*4096],wf2l[4096*4096];
__device__ __nv_bfloat16 wf3h[128*4096], wf3l[128*4096];

// ---------------- PTX helpers ----------------
__device__ __forceinline__ uint32_t smem_u32(const void* p) {
    uint32_t a;
    asm("{ .reg .u64 t; cvta.to.shared.u64 t, %1; cvt.u32.u64 %0, t; }" : "=r"(a) : "l"(p));
    return a;
}
__device__ __forceinline__ void ldsm4(uint32_t addr, uint32_t& r0, uint32_t& r1,
                                      uint32_t& r2, uint32_t& r3) {
    asm volatile("ldmatrix.sync.aligned.m8n8.x4.shared.b16 {%0,%1,%2,%3}, [%4];"
        : "=r"(r0), "=r"(r1), "=r"(r2), "=r"(r3) : "r"(addr));
}
__device__ __forceinline__ void mma16816(float* c, const uint32_t* a, const uint32_t* b) {
    asm volatile("mma.sync.aligned.m16n8k16.row.col.f32.bf16.bf16.f32 "
        "{%0,%1,%2,%3}, {%4,%5,%6,%7}, {%8,%9}, {%0,%1,%2,%3};"
        : "+f"(c[0]), "+f"(c[1]), "+f"(c[2]), "+f"(c[3])
        : "r"(a[0]), "r"(a[1]), "r"(a[2]), "r"(a[3]), "r"(b[0]), "r"(b[1]));
}
#define CP16(dst,src) asm volatile("cp.async.ca.shared.global [%0], [%1], 16;" :: "r"(dst), "l"(src) : "memory")
#define CPCOMMIT()    asm volatile("cp.async.commit_group;" ::: "memory")
#define CPWAIT0()     asm volatile("cp.async.wait_group 0;" ::: "memory")

__device__ __forceinline__ __nv_bfloat162 pack_split(float v) {
    __nv_bfloat162 r;
    r.x = __float2bfloat16(v);
    r.y = __float2bfloat16(v - __bfloat162float(r.x));
    return r;
}

// ---------------- weight prep: fp32 -> padded bf16 hi/lo planes ----------------
__global__ void prepW(const float* __restrict__ W, __nv_bfloat16* __restrict__ hi,
                      __nv_bfloat16* __restrict__ lo, int KD, int KP) {
    int k  = blockIdx.x * 256 + threadIdx.x;
    int oc = blockIdx.y;
    if (k >= KP) return;
    float v = (k < KD) ? W[(size_t)oc * KD + k] : 0.f;
    __nv_bfloat16 h = __float2bfloat16(v);
    hi[(size_t)oc * KP + k] = h;
    lo[(size_t)oc * KP + k] = __float2bfloat16(v - __bfloat162float(h));
}

// ---------------- pipelined tensor-core GEMM ----------------
// D[p][oc] = sum_k A[p,k]*W[oc,k], fp32 accum, 3-term bf16 split.
// BM=128, BN in {64,96,128}, BK=32. 8 warps: 4(m) x 2(n); warp = 32 x BN/2.
// ASRC: 0 = fp32 im2col (conv1), 1 = bf162 im2col (conv2-5), 2 = bf162 dense (fc).
template<int BN, int KDIM, int KSLICE, int OCTOT, bool RELU, bool PARTIAL, int ASRC,
         int CIN, int KW, int S, int PD, int HIN, int HOUT>
__global__ __launch_bounds__(256) void tc2(
    const void* __restrict__ Ain,
    const __nv_bfloat16* __restrict__ Whi, const __nv_bfloat16* __restrict__ Wlo,
    int KPADW,
    const float* __restrict__ bias,
    __nv_bfloat162* __restrict__ outbf, float* __restrict__ outpart)
{
    constexpr int CH  = KSLICE / 32;
    constexpr int NP  = BN / 32;             // 16-col B groups per warp
    constexpr int NT  = 2 * NP;              // 8-col tiles per warp
    constexpr int KKc = KW * KW;
    constexpr int HW  = HOUT * HOUT;
    constexpr int ABYTES = 128 * 40 * 2;     // 10240
    constexpr int BBYTES = BN * 40 * 2;
    constexpr int STGB   = 2 * ABYTES + 2 * BBYTES;

    extern __shared__ __align__(16) char smem[];

    const int tid = threadIdx.x, wid = tid >> 5, lane = tid & 31;
    const int wm = wid & 3, wn = wid >> 2;
    const int ocBase = blockIdx.y * BN;
    const int kb0    = blockIdx.z * KSLICE;

    // A decode
    const int row = tid >> 1;
    const int c0  = (tid & 1) * 16;
    const int p   = blockIdx.x * 128 + row;
    int ihb = 0, iwb = 0, nIdx = 0;
    if (ASRC != 2) {
        int n = p / HW; int q = p - n * HW;
        int oh = q / HOUT, ow = q - oh * HOUT;
        ihb = oh * S - PD; iwb = ow * S - PD; nIdx = n;
    }

    float acc[2][NT][4];
    #pragma unroll
    for (int i = 0; i < 2; i++)
        #pragma unroll
        for (int j = 0; j < NT; j++)
            #pragma unroll
            for (int k = 0; k < 4; k++) acc[i][j][k] = 0.f;

    auto prefetchA = [&](int kb, uint32_t* ar) {
        #pragma unroll
        for (int cc = 0; cc < 16; cc++) {
            int k = kb + c0 + cc;
            if (ASRC == 2) {
                ar[cc] = __ldg(&((const uint32_t*)Ain)[(size_t)p * KDIM + k]);
            } else {
                uint32_t v = 0;
                bool kok = ((KDIM & 31) == 0) || (k < KDIM);
                if (kok) {
                    int ic = k / KKc; int r2 = k - ic * KKc;
                    int kh = r2 / KW; int kw2 = r2 - kh * KW;
                    int ih = ihb + kh, iw = iwb + kw2;
                    if (ih >= 0 && ih < HIN && iw >= 0 && iw < HIN) {
                        size_t idx = ((size_t)nIdx * CIN + ic) * (HIN * HIN) + ih * HIN + iw;
                        v = __ldg(&((const uint32_t*)Ain)[idx]);
                    }
                }
                ar[cc] = v;
            }
        }
    };
    auto storeA = [&](char* base, uint32_t* ar) {
        #pragma unroll
        for (int cc = 0; cc < 16; cc += 2) {
            uint32_t h2, l2;
            if (ASRC == 0) {
                float v0 = __uint_as_float(ar[cc]), v1 = __uint_as_float(ar[cc + 1]);
                __nv_bfloat162 hp, lp;
                hp.x = __float2bfloat16(v0); hp.y = __float2bfloat16(v1);
                lp.x = __float2bfloat16(v0 - __bfloat162float(hp.x));
                lp.y = __float2bfloat16(v1 - __bfloat162float(hp.y));
                h2 = *(uint32_t*)&hp; l2 = *(uint32_t*)&lp;
            } else {
                // stored pair: low16 = hi, high16 = lo
                h2 = (ar[cc] & 0xffffu) | (ar[cc + 1] << 16);
                l2 = (ar[cc] >> 16) | (ar[cc + 1] & 0xffff0000u);
            }
            int byteoff = row * 80 + (c0 + cc) * 2;
            *(uint32_t*)(base + byteoff)          = h2;
            *(uint32_t*)(base + ABYTES + byteoff) = l2;
        }
    };
    auto fillB = [&](char* base, int kb) {
        for (int u = tid; u < BN * 8; u += 256) {
            int r = u >> 3, rem = u & 7, pl = rem >> 2, q = rem & 3;
            const __nv_bfloat16* src = (pl ? Wlo : Whi)
                + (size_t)(ocBase + r) * KPADW + kb + q * 8;
            uint32_t dst = smem_u32(base + 2 * ABYTES + pl * BBYTES + r * 80 + q * 16);
            CP16(dst, src);
        }
    };
    auto compute = [&](char* base) {
        uint32_t aH = smem_u32(base);
        uint32_t aL = aH + ABYTES, bH = aH + 2 * ABYTES, bL = bH + BBYTES;
        const int g = lane >> 3, rr = lane & 7;
        #pragma unroll
        for (int ks = 0; ks < 2; ks++) {
            const int kc = ks * 16;
            uint32_t fah[2][4], fal[2][4], fbh[NT][2], fbl[NT][2];
            #pragma unroll
            for (int mt = 0; mt < 2; mt++) {
                uint32_t off = (uint32_t)((wm*32 + mt*16 + (g&1)*8 + rr) * 40
                                          + kc + (g>>1)*8) * 2u;
                ldsm4(aH + off, fah[mt][0], fah[mt][1], fah[mt][2], fah[mt][3]);
                ldsm4(aL + off, fal[mt][0], fal[mt][1], fal[mt][2], fal[mt][3]);
            }
            #pragma unroll
            for (int np = 0; np < NP; np++) {
                uint32_t off = (uint32_t)((wn*(BN/2) + np*16 + (g>>1)*8 + rr) * 40
                                          + kc + (g&1)*8) * 2u;
                uint32_t r0, r1, r2, r3;
                ldsm4(bH + off, r0, r1, r2, r3);
                fbh[2*np][0]=r0; fbh[2*np][1]=r1; fbh[2*np+1][0]=r2; fbh[2*np+1][1]=r3;
                ldsm4(bL + off, r0, r1, r2, r3);
                fbl[2*np][0]=r0; fbl[2*np][1]=r1; fbl[2*np+1][0]=r2; fbl[2*np+1][1]=r3;
            }
            #pragma unroll
            for (int mt = 0; mt < 2; mt++)
                #pragma unroll
                for (int nt = 0; nt < NT; nt++) {
                    mma16816(acc[mt][nt], fah[mt], fbh[nt]);
                    mma16816(acc[mt][nt], fal[mt], fbh[nt]);
                    mma16816(acc[mt][nt], fah[mt], fbl[nt]);
                }
        }
    };

    uint32_t ar[16];
    // prologue: fill stage 0
    prefetchA(kb0, ar);
    fillB(smem, kb0);
    CPCOMMIT();
    storeA(smem, ar);
    CPWAIT0();
    __syncthreads();

    for (int ci = 0; ci < CH; ci++) {
        char* cur = smem + (ci & 1) * STGB;
        char* nxt = smem + ((ci + 1) & 1) * STGB;
        if (ci + 1 < CH) {
            prefetchA(kb0 + (ci + 1) * 32, ar);   // LDGs issue here, latency hidden by MMAs
            fillB(nxt, kb0 + (ci + 1) * 32);
            CPCOMMIT();
        }
        compute(cur);
        if (ci + 1 < CH) {
            storeA(nxt, ar);
            CPWAIT0();
        }
        __syncthreads();
    }

    // ---- epilogue ----
    #pragma unroll
    for (int mt = 0; mt < 2; mt++) {
        #pragma unroll
        for (int nt = 0; nt < NT; nt++) {
            int m0 = blockIdx.x * 128 + wm*32 + mt*16 + (lane >> 2);
            int n0 = ocBase + wn*(BN/2) + nt*8 + (lane & 3)*2;
            #pragma unroll
            for (int h = 0; h < 2; h++) {
                int pe = m0 + h * 8;
                if (PARTIAL) {
                    float2 v2 = make_float2(acc[mt][nt][h*2], acc[mt][nt][h*2+1]);
                    *(float2*)&outpart[(size_t)blockIdx.z * 128 * OCTOT
                                       + (size_t)pe * OCTOT + n0] = v2;
                } else {
                    #pragma unroll
                    for (int cidx = 0; cidx < 2; cidx++) {
                        int oc = n0 + cidx;
                        float v = acc[mt][nt][h*2 + cidx] + __ldg(&bias[oc]);
                        if (RELU) v = fmaxf(v, 0.f);
                        int ne = pe / HW; int qe = pe - ne * HW;
                        outbf[((size_t)ne * OCTOT + oc) * HW + qe] = pack_split(v);
                    }
                }
            }
        }
    }
}

// ---------------- split-K reduce: out = act(sum_z part + bias) ----------------
template<bool RELU, bool TOBF>
__global__ void reduceK(const float* __restrict__ part, const float* __restrict__ bias,
                        void* __restrict__ outp, int OCTOT, int NZ)
{
    int idx = blockIdx.x * 256 + threadIdx.x;
    int oc  = idx & (OCTOT - 1);
    float s = bias[oc];
    for (int z = 0; z < NZ; z++) s += part[(size_t)z * 128 * OCTOT + idx];
    if (RELU) s = fmaxf(s, 0.f);
    if (TOBF) ((__nv_bfloat162*)outp)[idx] = pack_split(s);
    else      ((float*)outp)[idx] = s;
}

// ---------------- 3x3 s2 VALID maxpool on bf162 pairs ----------------
template<int HIN, int HOUT>
__global__ void pool_bf(const __nv_bfloat162* __restrict__ in,
                        __nv_bfloat162* __restrict__ out, int total)
{
    int idx = blockIdx.x * 256 + threadIdx.x;
    if (idx >= total) return;
    int ow = idx % HOUT;
    int t  = idx / HOUT;
    int oh = t % HOUT;
    int nc = t / HOUT;
    const __nv_bfloat162* pp = in + (size_t)nc * HIN * HIN + (oh * 2) * HIN + ow * 2;
    float best = -1e30f; __nv_bfloat162 bp = pp[0];
    #pragma unroll
    for (int a = 0; a < 3; a++)
        #pragma unroll
        for (int b = 0; b < 3; b++) {
            __nv_bfloat162 tv = pp[a * HIN + b];
            float v = __bfloat162float(tv.x) + __bfloat162float(tv.y);
            if (v > best) { best = v; bp = tv; }
        }
    out[idx] = bp;
}

// ---------------- PQ head (unchanged, proven) ----------------
__global__ void pq_head(const float* __restrict__ h, const float* __restrict__ cb,
                        float* __restrict__ gsoft, float* __restrict__ oh_,
                        float* __restrict__ ohard, float* __restrict__ osoft)
{
    __shared__ float xs[32];
    __shared__ float pe[256];
    __shared__ float sv[256];
    __shared__ int   si[256];

    const int tid = threadIdx.x;
    const int b = blockIdx.x >> 2;
    const int l = blockIdx.x & 3;

    if (tid < 32) xs[tid] = h[b*128 + l*32 + tid];
    __syncthreads();

    float xn2 = 0.f;
    #pragma unroll
    for (int d=0; d<32; d++) xn2 += xs[d]*xs[d];

    const float* cbl = cb + (l*256)*32;
    const float* ck  = cbl + tid*32;
    float dot=0.f, cn2=0.f;
    #pragma unroll
    for (int d=0; d<32; d++) { float c = ck[d]; dot += xs[d]*c; cn2 += c*c; }
    float s = dot / fmaxf(sqrtf(xn2)*sqrtf(cn2), 1e-8f);

    sv[tid]=s; si[tid]=tid;
    __syncthreads();
    for (int off=128; off>0; off>>=1) {
        if (tid<off) {
            float ov=sv[tid+off]; int oi=si[tid+off];
            if (ov>sv[tid] || (ov==sv[tid] && oi<si[tid])) { sv[tid]=ov; si[tid]=oi; }
        }
        __syncthreads();
    }
    float mx = sv[0]; int idx = si[0];
    __syncthreads();

    float e = expf(20.f*(s - mx));
    pe[tid]=e; sv[tid]=e;
    __syncthreads();
    for (int off=128; off>0; off>>=1) {
        if (tid<off) sv[tid] += sv[tid+off];
        __syncthreads();
    }
    float denom = sv[0];

    if (tid < 32) {
        float acc = 0.f;
        for (int k=0;k<256;k++) acc += pe[k]*cbl[k*32+tid];
        acc /= denom;
        float n2 = acc*acc;
        #pragma unroll
        for (int m=16;m;m>>=1) n2 += __shfl_xor_sync(0xffffffffu, n2, m);
        float svv = acc / fmaxf(sqrtf(n2), 1e-12f);
        int o = b*128 + l*32 + tid;
        osoft[o] = svv;
        gsoft[o] = svv;
        float c = cbl[idx*32+tid];
        float h2 = c*c;
        #pragma unroll
        for (int m=16;m;m>>=1) h2 += __shfl_xor_sync(0xffffffffu, h2, m);
        ohard[o] = c / fmaxf(sqrtf(h2), 1e-12f);
        oh_[o] = xs[tid];
    }
}

// ---------------- recon ----------------
__global__ void recon_kernel(const float* __restrict__ soft, const float* __restrict__ rw,
                             float* __restrict__ out)
{
    __shared__ float s[128];
    const int b = blockIdx.x, tid = threadIdx.x;
    if (tid < 128) s[tid] = soft[b*128 + tid];
    __syncthreads();
    for (int r = tid; r < 300; r += 256) {
        const float* wr = rw + r*128;
        float a = 0.f;
        #pragma unroll 8
        for (int k=0;k<128;k++) a += s[k]*wr[k];
        out[b*300 + r] = a > 0.f ? a : 0.01f*a;
    }
}

// ---------------- launch ----------------
extern "C" void kernel_launch(void* const* d_in, const int* in_sizes, int n_in,
                              void* d_out, int out_size)
{
    const float* x   = (const float*)d_in[0];
    const float* w1  = (const float*)d_in[1];
    const float* b1  = (const float*)d_in[2];
    const float* w2  = (const float*)d_in[3];
    const float* b2  = (const float*)d_in[4];
    const float* w3  = (const float*)d_in[5];
    const float* b3  = (const float*)d_in[6];
    const float* w4  = (const float*)d_in[7];
    const float* b4  = (const float*)d_in[8];
    const float* w5  = (const float*)d_in[9];
    const float* b5  = (const float*)d_in[10];
    const float* cw1 = (const float*)d_in[11];
    const float* cb1 = (const float*)d_in[12];
    const float* cw2 = (const float*)d_in[13];
    const float* cb2 = (const float*)d_in[14];
    const float* fw  = (const float*)d_in[15];
    const float* fb  = (const float*)d_in[16];
    const float* cbk = (const float*)d_in[17];
    const float* rw  = (const float*)d_in[18];

    float* out = (float*)d_out;
    float* out_h    = out;
    float* out_hard = out + 16384;
    float* out_soft = out + 32768;
    float* out_rec  = out + 49152;

    __nv_bfloat162 *c1,*p1,*c2,*p2,*c3,*c4,*c5,*p5,*f1,*f2;
    float *hh,*sf,*part;
    __nv_bfloat16 *W1h,*W1l,*W2h,*W2l,*W3h,*W3l,*W4h,*W4l,*W5h,*W5l,*F1h,*F1l,*F2h,*F2l,*F3h,*F3l;
    cudaGetSymbolAddress((void**)&c1, g_conv1);  cudaGetSymbolAddress((void**)&p1, g_pool1);
    cudaGetSymbolAddress((void**)&c2, g_conv2);  cudaGetSymbolAddress((void**)&p2, g_pool2);
    cudaGetSymbolAddress((void**)&c3, g_conv3);  cudaGetSymbolAddress((void**)&c4, g_conv4);
    cudaGetSymbolAddress((void**)&c5, g_conv5);  cudaGetSymbolAddress((void**)&p5, g_pool5);
    cudaGetSymbolAddress((void**)&f1, g_fc1);    cudaGetSymbolAddress((void**)&f2, g_fc2);
    cudaGetSymbolAddress((void**)&hh, g_h);      cudaGetSymbolAddress((void**)&sf, g_soft);
    cudaGetSymbolAddress((void**)&part, g_part);
    cudaGetSymbolAddress((void**)&W1h, wp1h);  cudaGetSymbolAddress((void**)&W1l, wp1l);
    cudaGetSymbolAddress((void**)&W2h, wp2h);  cudaGetSymbolAddress((void**)&W2l, wp2l);
    cudaGetSymbolAddress((void**)&W3h, wp3h);  cudaGetSymbolAddress((void**)&W3l, wp3l);
    cudaGetSymbolAddress((void**)&W4h, wp4h);  cudaGetSymbolAddress((void**)&W4l, wp4l);
    cudaGetSymbolAddress((void**)&W5h, wp5h);  cudaGetSymbolAddress((void**)&W5l, wp5l);
    cudaGetSymbolAddress((void**)&F1h, wf1h);  cudaGetSymbolAddress((void**)&F1l, wf1l);
    cudaGetSymbolAddress((void**)&F2h, wf2h);  cudaGetSymbolAddress((void**)&F2l, wf2l);
    cudaGetSymbolAddress((void**)&F3h, wf3h);  cudaGetSymbolAddress((void**)&F3l, wf3l);

    // instantiations
    auto* k1  = tc2<64, 363, 384, 64, true, false, 0, 3,11,4,2,224,55>;
    auto* k2  = tc2<96, 1600,1600,192, true, false, 1, 64,5,1,2,27,27>;
    auto* k3  = tc2<128,1728,1728,384, true, false, 1, 192,3,1,1,13,13>;
    auto* k4  = tc2<128,3456,3456,256, true, false, 1, 384,3,1,1,13,13>;
    auto* k5  = tc2<128,2304,2304,256, true, false, 1, 256,3,1,1,13,13>;
    auto* kf1 = tc2<128,9216,1152,4096,false, true, 2, 1,1,1,0,1,1>;
    auto* kf2 = tc2<128,4096,1024,4096,false, true, 2, 1,1,1,0,1,1>;
    auto* kf3 = tc2<128,4096, 512, 128,false, true, 2, 1,1,1,0,1,1>;

    const int SM64  = 2*(2*10240 + 2*64*80);    // 61440
    const int SM96  = 2*(2*10240 + 2*96*80);    // 71680
    const int SM128 = 2*(2*10240 + 2*128*80);   // 81920
    cudaFuncSetAttribute(k1,  cudaFuncAttributeMaxDynamicSharedMemorySize, SM64);
    cudaFuncSetAttribute(k2,  cudaFuncAttributeMaxDynamicSharedMemorySize, SM96);
    cudaFuncSetAttribute(k3,  cudaFuncAttributeMaxDynamicSharedMemorySize, SM128);
    cudaFuncSetAttribute(k4,  cudaFuncAttributeMaxDynamicSharedMemorySize, SM128);
    cudaFuncSetAttribute(k5,  cudaFuncAttributeMaxDynamicSharedMemorySize, SM128);
    cudaFuncSetAttribute(kf1, cudaFuncAttributeMaxDynamicSharedMemorySize, SM128);
    cudaFuncSetAttribute(kf2, cudaFuncAttributeMaxDynamicSharedMemorySize, SM128);
    cudaFuncSetAttribute(kf3, cudaFuncAttributeMaxDynamicSharedMemorySize, SM128);

    // ---- weight prep ----
    prepW<<<dim3(2,   64),  256>>>(w1,  W1h, W1l, 363,  384);
    prepW<<<dim3(7,   192), 256>>>(w2,  W2h, W2l, 1600, 1600);
    prepW<<<dim3(7,   384), 256>>>(w3,  W3h, W3l, 1728, 1728);
    prepW<<<dim3(14,  256), 256>>>(w4,  W4h, W4l, 3456, 3456);
    prepW<<<dim3(9,   256), 256>>>(w5,  W5h, W5l, 2304, 2304);
    prepW<<<dim3(36, 4096), 256>>>(cw1, F1h, F1l, 9216, 9216);
    prepW<<<dim3(16, 4096), 256>>>(cw2, F2h, F2l, 4096, 4096);
    prepW<<<dim3(16,  128), 256>>>(fw,  F3h, F3l, 4096, 4096);

    // ---- conv stack ----
    k1<<<dim3(3025,1,1), 256, SM64 >>>(x,  W1h, W1l, 384,  b1, c1, nullptr);
    pool_bf<55,27><<<(128*64*27*27 + 255)/256, 256>>>(c1, p1, 128*64*27*27);
    k2<<<dim3(729, 2,1), 256, SM96 >>>(p1, W2h, W2l, 1600, b2, c2, nullptr);
    pool_bf<27,13><<<(128*192*13*13 + 255)/256, 256>>>(c2, p2, 128*192*13*13);
    k3<<<dim3(169, 3,1), 256, SM128>>>(p2, W3h, W3l, 1728, b3, c3, nullptr);
    k4<<<dim3(169, 2,1), 256, SM128>>>(c3, W4h, W4l, 3456, b4, c4, nullptr);
    k5<<<dim3(169, 2,1), 256, SM128>>>(c4, W5h, W5l, 2304, b5, c5, nullptr);
    pool_bf<13,6><<<(128*256*6*6 + 255)/256, 256>>>(c5, p5, 128*256*6*6);

    // ---- FC stack with split-K ----
    kf1<<<dim3(1,32,8), 256, SM128>>>(p5, F1h, F1l, 9216, nullptr, nullptr, part);
    reduceK<true, true ><<<2048, 256>>>(part, cb1, f1, 4096, 8);
    kf2<<<dim3(1,32,4), 256, SM128>>>(f1, F2h, F2l, 4096, nullptr, nullptr, part);
    reduceK<true, true ><<<2048, 256>>>(part, cb2, f2, 4096, 4);
    kf3<<<dim3(1,1,8),  256, SM128>>>(f2, F3h, F3l, 4096, nullptr, nullptr, part);
    reduceK<false,false><<<64,   256>>>(part, fb, hh, 128, 8);

    // ---- PQ head + recon ----
    pq_head<<<512,256>>>(hh, cbk, sf, out_h, out_hard, out_soft);
    recon_kernel<<<128,256>>>(sf, rw, out_rec);
}